// round 1
// baseline (speedup 1.0000x reference)
#include <cuda_runtime.h>

// Problem constants (fixed by the dataset)
#define BB   4
#define CC   32
#define HH   512
#define WW   1024
#define HOo  512
#define WOo  1024
#define NPIX (HH * WW)        // 524288 input pixels
#define NOUT (HOo * WOo)      // 524288 output pixels per plane
#define BC   (BB * CC)        // 128 planes
#define KPL  8                // planes processed per thread

__device__ __forceinline__ void red_v4(float* addr, float a, float b, float c, float d) {
    asm volatile("red.global.add.v4.f32 [%0], {%1, %2, %3, %4};"
                 :: "l"(addr), "f"(a), "f"(b), "f"(c), "f"(d)
                 : "memory");
}

__device__ __forceinline__ void red_f(float* addr, float a) {
    asm volatile("red.global.add.f32 [%0], %1;"
                 :: "l"(addr), "f"(a)
                 : "memory");
}

__global__ __launch_bounds__(256)
void splat_kernel(const float* __restrict__ xin,
                  const float2* __restrict__ smap,
                  float* __restrict__ out) {
    int p = blockIdx.x * blockDim.x + threadIdx.x;
    if (p >= NPIX) return;
    const int bc0 = blockIdx.y * KPL;

    float2 s = __ldg(&smap[p]);
    float x0f = floorf(s.x);
    float y0f = floorf(s.y);
    float wx = s.x - x0f;
    float wy = s.y - y0f;
    int x0 = (int)x0f;
    int y0 = (int)y0f;
    float omx = 1.0f - wx;
    float omy = 1.0f - wy;
    float w00 = omx * omy;
    float w10 = wx  * omy;
    float w01 = omx * wy;
    float w11 = wx  * wy;

    int lane = x0 & 3;
    // Fast path: both horizontal corners of each row fit inside one 16B-aligned
    // float4, and row-0 is fully in bounds (row-1 guarded separately).
    bool fast = (lane < 3) & (x0 >= 0) & (x0 + 1 < WOo) & (y0 >= 0) & (y0 < HOo);

    if (fast) {
        long long base0 = (long long)y0 * WOo + (x0 & ~3);
        bool row1 = (y0 + 1) < HOo;

        // Row-0 weight vector: w00 at component `lane`, w10 at `lane+1`.
        float a0 = (lane == 0) ? w00 : 0.0f;
        float b0 = (lane == 1) ? w00 : ((lane == 0) ? w10 : 0.0f);
        float c0 = (lane == 2) ? w00 : ((lane == 1) ? w10 : 0.0f);
        float d0 = (lane == 2) ? w10 : 0.0f;
        // Row-1 weight vector: w01 / w11 at the same components.
        float a1 = (lane == 0) ? w01 : 0.0f;
        float b1 = (lane == 1) ? w01 : ((lane == 0) ? w11 : 0.0f);
        float c1 = (lane == 2) ? w01 : ((lane == 1) ? w11 : 0.0f);
        float d1 = (lane == 2) ? w11 : 0.0f;

        #pragma unroll
        for (int k = 0; k < KPL; k++) {
            long long plane = (long long)(bc0 + k) * (long long)NOUT;
            float v = __ldg(&xin[(long long)(bc0 + k) * (long long)NPIX + p]);
            float* o0 = out + plane + base0;
            red_v4(o0, a0 * v, b0 * v, c0 * v, d0 * v);
            if (row1) {
                red_v4(o0 + WOo, a1 * v, b1 * v, c1 * v, d1 * v);
            }
        }
    } else {
        // Fully-guarded scalar path (lane==3, or any out-of-range corner).
        int x1 = x0 + 1;
        int y1 = y0 + 1;
        bool vx0 = (x0 >= 0) & (x0 < WOo);
        bool vx1 = (x1 >= 0) & (x1 < WOo);
        bool vy0 = (y0 >= 0) & (y0 < HOo);
        bool vy1 = (y1 >= 0) & (y1 < HOo);

        #pragma unroll
        for (int k = 0; k < KPL; k++) {
            long long plane = (long long)(bc0 + k) * (long long)NOUT;
            float v = __ldg(&xin[(long long)(bc0 + k) * (long long)NPIX + p]);
            if (vy0) {
                long long r0 = plane + (long long)y0 * WOo;
                if (vx0) red_f(out + r0 + x0, w00 * v);
                if (vx1) red_f(out + r0 + x1, w10 * v);
            }
            if (vy1) {
                long long r1 = plane + (long long)y1 * WOo;
                if (vx0) red_f(out + r1 + x0, w01 * v);
                if (vx1) red_f(out + r1 + x1, w11 * v);
            }
        }
    }
}

extern "C" void kernel_launch(void* const* d_in, const int* in_sizes, int n_in,
                              void* d_out, int out_size) {
    const float*  x    = (const float*)d_in[0];
    const float2* smap = (const float2*)d_in[1];
    float*        out  = (float*)d_out;

    // Output must start at zero (harness poisons it with 0xAA).
    cudaMemsetAsync(out, 0, (size_t)out_size * sizeof(float), 0);

    dim3 block(256);
    dim3 grid((NPIX + block.x - 1) / block.x, BC / KPL);
    splat_kernel<<<grid, block>>>(x, smap, out);
}

// round 2
// speedup vs baseline: 3.1084x; 3.1084x over previous
#include <cuda_runtime.h>

// Problem constants (fixed by the dataset)
#define HH   512
#define WW   1024
#define HOo  512
#define WOo  1024
#define NPIX (HH * WW)          // 524288 input pixels
#define NOUT (HOo * WOo)        // 524288 output cells per plane
#define NPLANE 128              // B*C

// ---- static device scratch (allowed; no runtime allocation) ----
__device__ float g_xt[(size_t)NPIX * NPLANE];   // 256MB: x transposed [pixel][plane]
__device__ int   g_count[NOUT];                 // contributions per output cell
__device__ int   g_off[NOUT];                   // start offset per cell
__device__ int   g_cursor[NOUT];                // scatter cursor per cell
__device__ int   g_alloc;                       // global allocation counter
__device__ int2  g_entry[(size_t)NPIX * 4];     // 16MB: {pixel, weight as bits}

// ---------------------------------------------------------------
// K1: transpose x [128][NPIX] -> g_xt [NPIX][128]
__global__ __launch_bounds__(256)
void transpose_k(const float* __restrict__ x) {
    __shared__ float tile[32][33];
    int p0 = blockIdx.x * 32;           // pixel tile base
    int c0 = blockIdx.y * 32;           // plane tile base
    int tx = threadIdx.x, ty = threadIdx.y;   // block (32,8)
    #pragma unroll
    for (int i = ty; i < 32; i += 8)
        tile[i][tx] = x[(size_t)(c0 + i) * NPIX + p0 + tx];
    __syncthreads();
    #pragma unroll
    for (int i = ty; i < 32; i += 8)
        g_xt[(size_t)(p0 + i) * NPLANE + c0 + tx] = tile[tx][i];
}

// K2: clear counters
__global__ __launch_bounds__(256)
void clear_k() {
    int i = blockIdx.x * blockDim.x + threadIdx.x;
    if (i < NOUT) g_count[i] = 0;
    if (i == 0) g_alloc = 0;
}

// helper: the 4 corners of a pixel's splat
struct Corners {
    int cell[4]; float w[4]; int valid[4];
};
__device__ __forceinline__ Corners make_corners(float2 s) {
    Corners c;
    float x0f = floorf(s.x), y0f = floorf(s.y);
    float wx = s.x - x0f, wy = s.y - y0f;
    int x0 = (int)x0f, y0 = (int)y0f;
    int xs[4] = {x0, x0 + 1, x0,     x0 + 1};
    int ys[4] = {y0, y0,     y0 + 1, y0 + 1};
    float ws[4] = {(1.f - wx) * (1.f - wy), wx * (1.f - wy),
                   (1.f - wx) * wy,         wx * wy};
    #pragma unroll
    for (int k = 0; k < 4; k++) {
        c.valid[k] = ((unsigned)xs[k] < (unsigned)WOo) &
                     ((unsigned)ys[k] < (unsigned)HOo);
        c.cell[k]  = ys[k] * WOo + xs[k];
        c.w[k]     = ws[k];
    }
    return c;
}

// K3: histogram of contributions per output cell
__global__ __launch_bounds__(256)
void hist_k(const float2* __restrict__ smap) {
    int p = blockIdx.x * blockDim.x + threadIdx.x;
    if (p >= NPIX) return;
    Corners c = make_corners(__ldg(&smap[p]));
    #pragma unroll
    for (int k = 0; k < 4; k++)
        if (c.valid[k]) atomicAdd(&g_count[c.cell[k]], 1);
}

// K4: block-local exclusive scan + global allocation -> per-cell offsets
__global__ __launch_bounds__(1024)
void scan_alloc_k() {
    int tid = threadIdx.x;
    int cell = blockIdx.x * 1024 + tid;
    int cnt = g_count[cell];
    int lane = tid & 31, wid = tid >> 5;

    // inclusive warp scan
    int v = cnt;
    #pragma unroll
    for (int d = 1; d < 32; d <<= 1) {
        int t = __shfl_up_sync(0xFFFFFFFFu, v, d);
        if (lane >= d) v += t;
    }
    __shared__ int wsum[32];
    if (lane == 31) wsum[wid] = v;
    __syncthreads();
    if (wid == 0) {
        int s = wsum[lane];
        #pragma unroll
        for (int d = 1; d < 32; d <<= 1) {
            int t = __shfl_up_sync(0xFFFFFFFFu, s, d);
            if (lane >= d) s += t;
        }
        wsum[lane] = s;
    }
    __syncthreads();
    int incl = v + (wid ? wsum[wid - 1] : 0);
    __shared__ int base_s;
    if (tid == 0) base_s = atomicAdd(&g_alloc, wsum[31]);
    __syncthreads();
    int off = base_s + incl - cnt;   // exclusive position
    g_off[cell] = off;
    g_cursor[cell] = off;
}

// K5: scatter (pixel, weight) entries into per-cell ranges
__global__ __launch_bounds__(256)
void scatter_k(const float2* __restrict__ smap) {
    int p = blockIdx.x * blockDim.x + threadIdx.x;
    if (p >= NPIX) return;
    Corners c = make_corners(__ldg(&smap[p]));
    #pragma unroll
    for (int k = 0; k < 4; k++) {
        if (c.valid[k]) {
            int pos = atomicAdd(&g_cursor[c.cell[k]], 1);
            g_entry[pos] = make_int2(p, __float_as_int(c.w[k]));
        }
    }
}

// K6: gather — each warp: one cell x 32-plane group (x4 groups in regs),
// stage in shared, coalesced store. No atomics, fully overwrites d_out.
#define CELLS_PER_BLOCK 64
__global__ __launch_bounds__(256)
void gather_k(float* __restrict__ out) {
    __shared__ float acc_s[CELLS_PER_BLOCK][NPLANE + 1];  // +1 pad: conflict-free transpose read
    int tid = threadIdx.x;
    int lane = tid & 31, wid = tid >> 5;            // 8 warps
    int cell0 = blockIdx.x * CELLS_PER_BLOCK;

    for (int ci = wid; ci < CELLS_PER_BLOCK; ci += 8) {
        int cell = cell0 + ci;
        int beg = __ldg(&g_off[cell]);
        int cnt = __ldg(&g_count[cell]);
        float a0 = 0.f, a1 = 0.f, a2 = 0.f, a3 = 0.f;
        for (int e = 0; e < cnt; e++) {
            int2 en = __ldg(&g_entry[beg + e]);     // warp-uniform broadcast
            float w = __int_as_float(en.y);
            const float* row = &g_xt[(size_t)en.x * NPLANE];
            a0 = fmaf(w, __ldg(&row[lane]),      a0);
            a1 = fmaf(w, __ldg(&row[32 + lane]), a1);
            a2 = fmaf(w, __ldg(&row[64 + lane]), a2);
            a3 = fmaf(w, __ldg(&row[96 + lane]), a3);
        }
        acc_s[ci][lane]      = a0;
        acc_s[ci][32 + lane] = a1;
        acc_s[ci][64 + lane] = a2;
        acc_s[ci][96 + lane] = a3;
    }
    __syncthreads();

    // write out[plane][cell0..cell0+63], coalesced 256B per 64 threads
    for (int idx = tid; idx < CELLS_PER_BLOCK * NPLANE; idx += 256) {
        int plane = idx >> 6;
        int c = idx & (CELLS_PER_BLOCK - 1);
        out[(size_t)plane * NOUT + cell0 + c] = acc_s[c][plane];
    }
}

// ---------------------------------------------------------------
extern "C" void kernel_launch(void* const* d_in, const int* in_sizes, int n_in,
                              void* d_out, int out_size) {
    const float*  x    = (const float*)d_in[0];
    const float2* smap = (const float2*)d_in[1];
    float*        out  = (float*)d_out;

    // K2 + K1 (independent of each other, both before K3..K6)
    clear_k<<<(NOUT + 255) / 256, 256>>>();
    {
        dim3 b(32, 8);
        dim3 g(NPIX / 32, NPLANE / 32);
        transpose_k<<<g, b>>>(x);
    }
    hist_k<<<(NPIX + 255) / 256, 256>>>(smap);
    scan_alloc_k<<<NOUT / 1024, 1024>>>();
    scatter_k<<<(NPIX + 255) / 256, 256>>>(smap);
    gather_k<<<NOUT / CELLS_PER_BLOCK, 256>>>(out);
}